// round 14
// baseline (speedup 1.0000x reference)
#include <cuda_runtime.h>
#include <math.h>

#define NMAX 100000
#define EMAX 3200000
#define FIN  512
#define HID  16
#define NCLS 40
#define CAP  128          // max neighbors per node (Poisson(32): P(deg>=128) ~ e^-60)
#define TB   256
#define GROWS 64
#define GKT  32
#define XPAD (GKT + 1)

// ---- static scratch (no allocations; zero-initialized at module load) ----
__device__ int   g_cnt[NMAX];               // degree counters; ZERO at entry & exit of every call
__device__ int   g_col[NMAX * CAP];         // bucketed adjacency: node v's srcs at v*CAP
__device__ float g_dinv[NMAX];
__device__ __align__(128) float g_h [NMAX * HID];  // h = x@W1, then scaled in-place: hs = dinv*h
__device__ __align__(128) float g_h2[NMAX * HID];  // hs2 = dinv * relu(agg1+b1)
__device__ unsigned g_bcnt[4];              // barrier arrive counters (reset by last arriver)
__device__ volatile unsigned g_bflag[4];    // barrier generation flags (monotonic)

// packed f32x2 helpers (Blackwell)
#define PACK2(d, lo, hi) \
    asm("mov.b64 %0, {%1, %2};" : "=l"(d) : "f"(lo), "f"(hi))
#define UNPACK2(lo, hi, s) \
    asm("mov.b64 {%0, %1}, %2;" : "=f"(lo), "=f"(hi) : "l"(s))
#define FMA2(d, a, b, c) \
    asm("fma.rn.f32x2 %0, %1, %2, %3;" : "=l"(d) : "l"(a), "l"(b), "l"(c))

// sense-reversing grid barrier: safe across graph replays (count self-resets,
// flag is monotonic and compared against a pre-arrival snapshot).
__device__ __forceinline__ void grid_bar(int i, unsigned G) {
    __threadfence();            // release: make this thread's writes visible
    __syncthreads();            // all block threads' fences done before arrive
    if (threadIdx.x == 0) {
        unsigned saved = g_bflag[i];
        unsigned old = atomicAdd(&g_bcnt[i], 1);
        if (old == G - 1) {
            g_bcnt[i] = 0;      // reset for next use (next call)
            __threadfence();
            g_bflag[i] = saved + 1;
        } else {
            while (g_bflag[i] == saved) __nanosleep(64);
        }
    }
    __syncthreads();
    __threadfence();            // acquire: order subsequent loads
}

__global__ __launch_bounds__(TB) void k_mega(
    const float* __restrict__ x,  const float* __restrict__ W1,
    const float* __restrict__ b1, const float* __restrict__ W2,
    const float* __restrict__ b2, const int* __restrict__ ei,
    float* __restrict__ out, int n, int e, unsigned G)
{
    __shared__ __align__(16) unsigned long long wall[FIN][8];  // W1 col-pairs, 32 KB
    __shared__ float xs[GROWS][XPAD];                          // 8.4 KB
    __shared__ float w2s[HID * NCLS];
    __shared__ float b2s[NCLS];

    int t = threadIdx.x;
    unsigned bid = blockIdx.x;
    int wid = t >> 5, lane = t & 31;

    // ================= Phase A1: bucket fill (cnt was zero at entry) =================
    {
        int ep = (e + 1) >> 1;
        for (long i = (long)bid * TB + t; i < ep; i += (long)G * TB) {
            int i2 = (int)(i * 2);
            if (i2 + 1 < e) {
                int2 s = *(const int2*)&ei[i2];
                int2 d = *(const int2*)&ei[e + i2];
                int p0 = atomicAdd(&g_cnt[d.x], 1);
                int p1 = atomicAdd(&g_cnt[d.y], 1);
                if (p0 < CAP) g_col[(d.x << 7) + p0] = s.x;
                if (p1 < CAP) g_col[(d.y << 7) + p1] = s.y;
            } else if (i2 < e) {
                int s = ei[i2];
                int d = ei[e + i2];
                int p = atomicAdd(&g_cnt[d], 1);
                if (p < CAP) g_col[(d << 7) + p] = s;
            }
        }
    }

    // ================= Phase A2: gemm tiles h = x @ W1 =================
    {
        // W1 whole matrix into smem as packed (col 2cp, col 2cp+1) pairs
        for (int idx = t; idx < FIN * 8; idx += TB) {
            int kk = idx >> 3, cp = idx & 7;
            float w0 = W1[kk * HID + cp * 2];
            float w1 = W1[kk * HID + cp * 2 + 1];
            unsigned long long p; PACK2(p, w0, w1);
            wall[kk][cp] = p;
        }
        __syncthreads();

        int ntiles = (n + GROWS - 1) / GROWS;
        int r = t >> 2, cq = t & 3;        // row 0..63, col-group 0..3
        int c = t & 7,  rb = t >> 3;       // loader: k-chunk, row-base 0..31
        for (int tile = bid; tile < ntiles; tile += (int)G) {
            int r0 = tile * GROWS;
            unsigned long long acc0 = 0ull, acc1 = 0ull;
            for (int kt = 0; kt < FIN; kt += GKT) {
#pragma unroll
                for (int i = 0; i < 2; i++) {
                    int row = rb + 32 * i;
                    int gr = r0 + row;
                    float4 v = make_float4(0.f, 0.f, 0.f, 0.f);
                    if (gr < n) v = *(const float4*)&x[(long)gr * FIN + kt + c * 4];
                    xs[row][c * 4 + 0] = v.x;
                    xs[row][c * 4 + 1] = v.y;
                    xs[row][c * 4 + 2] = v.z;
                    xs[row][c * 4 + 3] = v.w;
                }
                __syncthreads();
#pragma unroll
                for (int k = 0; k < GKT; k++) {
                    float a = xs[r][k];                    // 8 banks, 4-way bcast: CF
                    unsigned long long pa; PACK2(pa, a, a);
                    FMA2(acc0, pa, wall[kt + k][cq * 2],     acc0);
                    FMA2(acc1, pa, wall[kt + k][cq * 2 + 1], acc1);
                }
                __syncthreads();
            }
            int gr = r0 + r;
            if (gr < n) {
                float o0, o1, o2, o3;
                UNPACK2(o0, o1, acc0);
                UNPACK2(o2, o3, acc1);
                *(float4*)&g_h[gr * HID + cq * 4] = make_float4(o0, o1, o2, o3);
            }
        }
    }

    grid_bar(0, G);

    // ================= Phase B: dinv + in-place scale h -> hs =================
    for (int idx = bid * TB + t; idx < n * 4; idx += (int)G * TB) {
        int v = idx >> 2, fq = idx & 3;
        float dv = rsqrtf((float)(g_cnt[v] + 1));   // self-loop adds 1
        if (fq == 0) g_dinv[v] = dv;
        float4* hp = (float4*)&g_h[v * HID + fq * 4];
        float4 h = *hp;
        h.x *= dv; h.y *= dv; h.z *= dv; h.w *= dv;
        *hp = h;
    }

    grid_bar(1, G);

    // ================= Phase C: gather1 -> hs2 =================
    {
        int slot = lane >> 2, fq = lane & 3;
        float4 bb = *(const float4*)&b1[fq * 4];
        for (int v = bid * 8 + wid; v < n; v += (int)G * 8) {
            int beg = v << 7;
            int dg  = g_cnt[v];
            float4 acc = make_float4(0.f, 0.f, 0.f, 0.f);
            int j = slot;
            for (; j + 24 < dg; j += 32) {
                int s0 = __ldg(&g_col[beg + j]);
                int s1 = __ldg(&g_col[beg + j + 8]);
                int s2 = __ldg(&g_col[beg + j + 16]);
                int s3 = __ldg(&g_col[beg + j + 24]);
                float4 h0 = *(const float4*)&g_h[s0 * HID + fq * 4];
                float4 h1 = *(const float4*)&g_h[s1 * HID + fq * 4];
                float4 h2 = *(const float4*)&g_h[s2 * HID + fq * 4];
                float4 h3 = *(const float4*)&g_h[s3 * HID + fq * 4];
                acc.x += (h0.x + h1.x) + (h2.x + h3.x);
                acc.y += (h0.y + h1.y) + (h2.y + h3.y);
                acc.z += (h0.z + h1.z) + (h2.z + h3.z);
                acc.w += (h0.w + h1.w) + (h2.w + h3.w);
            }
#pragma unroll
            for (int u = 0; u < 3; u++) {
                int jj = j + u * 8;
                if (jj < dg) {
                    int s = __ldg(&g_col[beg + jj]);
                    float4 h = *(const float4*)&g_h[s * HID + fq * 4];
                    acc.x += h.x; acc.y += h.y; acc.z += h.z; acc.w += h.w;
                }
            }
#pragma unroll
            for (int off = 4; off <= 16; off <<= 1) {
                acc.x += __shfl_xor_sync(0xffffffffu, acc.x, off);
                acc.y += __shfl_xor_sync(0xffffffffu, acc.y, off);
                acc.z += __shfl_xor_sync(0xffffffffu, acc.z, off);
                acc.w += __shfl_xor_sync(0xffffffffu, acc.w, off);
            }
            float dv = g_dinv[v];
            float4 self = *(const float4*)&g_h[v * HID + fq * 4];
            float4 o;
            o.x = dv * fmaxf(dv * (acc.x + self.x) + bb.x, 0.0f);
            o.y = dv * fmaxf(dv * (acc.y + self.y) + bb.y, 0.0f);
            o.z = dv * fmaxf(dv * (acc.z + self.z) + bb.z, 0.0f);
            o.w = dv * fmaxf(dv * (acc.w + self.w) + bb.w, 0.0f);
            if (lane < 4) *(float4*)&g_h2[v * HID + fq * 4] = o;
        }
    }

    grid_bar(2, G);

    // ================= Phase D: gather2 + W2 + log_softmax; resets cnt =================
    {
        for (int idx = t; idx < HID * NCLS; idx += TB) w2s[idx] = W2[idx];
        if (t < NCLS) b2s[t] = b2[t];
        __syncthreads();

        int slot = lane >> 2, fq = lane & 3;
        for (int v = bid * 8 + wid; v < n; v += (int)G * 8) {
            int beg = v << 7;
            int dg  = g_cnt[v];
            if (lane == 0) g_cnt[v] = 0;   // restore invariant: cnt==0 at call exit
            float4 acc = make_float4(0.f, 0.f, 0.f, 0.f);
            int j = slot;
            for (; j + 24 < dg; j += 32) {
                int s0 = __ldg(&g_col[beg + j]);
                int s1 = __ldg(&g_col[beg + j + 8]);
                int s2 = __ldg(&g_col[beg + j + 16]);
                int s3 = __ldg(&g_col[beg + j + 24]);
                float4 h0 = *(const float4*)&g_h2[s0 * HID + fq * 4];
                float4 h1 = *(const float4*)&g_h2[s1 * HID + fq * 4];
                float4 h2 = *(const float4*)&g_h2[s2 * HID + fq * 4];
                float4 h3 = *(const float4*)&g_h2[s3 * HID + fq * 4];
                acc.x += (h0.x + h1.x) + (h2.x + h3.x);
                acc.y += (h0.y + h1.y) + (h2.y + h3.y);
                acc.z += (h0.z + h1.z) + (h2.z + h3.z);
                acc.w += (h0.w + h1.w) + (h2.w + h3.w);
            }
#pragma unroll
            for (int u = 0; u < 3; u++) {
                int jj = j + u * 8;
                if (jj < dg) {
                    int s = __ldg(&g_col[beg + jj]);
                    float4 h = *(const float4*)&g_h2[s * HID + fq * 4];
                    acc.x += h.x; acc.y += h.y; acc.z += h.z; acc.w += h.w;
                }
            }
#pragma unroll
            for (int off = 4; off <= 16; off <<= 1) {
                acc.x += __shfl_xor_sync(0xffffffffu, acc.x, off);
                acc.y += __shfl_xor_sync(0xffffffffu, acc.y, off);
                acc.z += __shfl_xor_sync(0xffffffffu, acc.z, off);
                acc.w += __shfl_xor_sync(0xffffffffu, acc.w, off);
            }
            float dv = g_dinv[v];
            float4 self = *(const float4*)&g_h2[v * HID + fq * 4];
            float av[4];
            av[0] = dv * (acc.x + self.x);
            av[1] = dv * (acc.y + self.y);
            av[2] = dv * (acc.z + self.z);
            av[3] = dv * (acc.w + self.w);

            float a[HID];
#pragma unroll
            for (int k = 0; k < HID; k++)
                a[k] = __shfl_sync(0xffffffffu, av[k & 3], k >> 2);

            float v1 = b2s[lane];
#pragma unroll
            for (int k = 0; k < HID; k++) v1 += a[k] * w2s[k * NCLS + lane];

            float v2 = __int_as_float(0xff800000);  // -inf
            if (lane < 8) {
                int c2 = 32 + lane;
                v2 = b2s[c2];
#pragma unroll
                for (int k = 0; k < HID; k++) v2 += a[k] * w2s[k * NCLS + c2];
            }

            float m = fmaxf(v1, v2);
#pragma unroll
            for (int off = 16; off >= 1; off >>= 1)
                m = fmaxf(m, __shfl_xor_sync(0xffffffffu, m, off));

            float se = __expf(v1 - m) + ((lane < 8) ? __expf(v2 - m) : 0.0f);
#pragma unroll
            for (int off = 16; off >= 1; off >>= 1)
                se += __shfl_xor_sync(0xffffffffu, se, off);

            float lse = __logf(se);
            out[v * NCLS + lane] = v1 - m - lse;
            if (lane < 8) out[v * NCLS + 32 + lane] = v2 - m - lse;
        }
    }
}

extern "C" void kernel_launch(void* const* d_in, const int* in_sizes, int n_in,
                              void* d_out, int out_size) {
    const float* x  = (const float*)d_in[0];
    const float* W1 = (const float*)d_in[1];
    const float* b1 = (const float*)d_in[2];
    const float* W2 = (const float*)d_in[3];
    const float* b2 = (const float*)d_in[4];
    const int*   ei = (const int*)d_in[5];   // int32: JAX x64 disabled

    int n = in_sizes[0] / FIN;
    int e = in_sizes[5] / 2;
    if (n > NMAX) n = NMAX;
    if (e > EMAX) e = EMAX;

    // One-time co-resident grid sizing (host APIs, no allocation).
    static unsigned G = 0;
    if (G == 0) {
        int bpm = 0, sms = 0, dev = 0;
        cudaGetDevice(&dev);
        cudaDeviceGetAttribute(&sms, cudaDevAttrMultiProcessorCount, dev);
        if (cudaOccupancyMaxActiveBlocksPerMultiprocessor(&bpm, k_mega, TB, 0)
                != cudaSuccess || bpm < 1) bpm = 1;
        if (sms < 1) sms = 1;
        G = (unsigned)(bpm * sms);
        if (G < 1) G = 1;
    }

    k_mega<<<G, TB>>>(x, W1, b1, W2, b2, ei, (float*)d_out, n, e, G);
}

// round 15
// speedup vs baseline: 1.9396x; 1.9396x over previous
#include <cuda_runtime.h>
#include <math.h>

#define NMAX 100000
#define EMAX 3200000
#define FIN  512
#define HID  16
#define NCLS 40
#define CAP  128          // max neighbors per node (Poisson(32): P(deg>=128) ~ e^-60)

// ---- static scratch (no allocations; zero-initialized at module load) ----
__device__ int   g_cnt[NMAX];               // degree counters; ZERO at entry & exit of every call
__device__ int   g_col[NMAX * CAP];         // bucketed adjacency: node v's srcs at v*CAP
__device__ float g_dinv[NMAX];
__device__ __align__(128) float g_h [NMAX * HID];  // h = x@W1, then scaled in-place: hs = dinv*h
__device__ __align__(128) float g_h2[NMAX * HID];  // hs2 = dinv * relu(agg1+b1)

// packed f32x2 helpers (Blackwell)
#define PACK2(d, lo, hi) \
    asm("mov.b64 %0, {%1, %2};" : "=l"(d) : "f"(lo), "f"(hi))
#define UNPACK2(lo, hi, s) \
    asm("mov.b64 {%0, %1}, %2;" : "=f"(lo), "=f"(hi) : "l"(s))
#define FMA2(d, a, b, c) \
    asm("fma.rn.f32x2 %0, %1, %2, %3;" : "=l"(d) : "l"(a), "l"(b), "l"(c))

// ---------------- bucket fill: cnt was left zero by the previous call ----------------
__global__ void k_fill(const int* __restrict__ ei, int e) {
    int i = blockIdx.x * blockDim.x + threadIdx.x;   // edge pair index
    int i2 = i * 2;
    if (i2 + 1 < e) {
        int2 s = *(const int2*)&ei[i2];
        int2 d = *(const int2*)&ei[e + i2];
        int p0 = atomicAdd(&g_cnt[d.x], 1);
        int p1 = atomicAdd(&g_cnt[d.y], 1);
        if (p0 < CAP) g_col[(d.x << 7) + p0] = s.x;
        if (p1 < CAP) g_col[(d.y << 7) + p1] = s.y;
    } else if (i2 < e) {
        int s = ei[i2];
        int d = ei[e + i2];
        int p = atomicAdd(&g_cnt[d], 1);
        if (p < CAP) g_col[(d << 7) + p] = s;
    }
}

// ---------------- dinv + in-place scale h -> hs (4 lanes per row) ----------------
__global__ __launch_bounds__(256) void k_dinv_scale(int n) {
    int idx = blockIdx.x * 256 + threadIdx.x;
    int v = idx >> 2, fq = idx & 3;
    if (v >= n) return;
    float dv = rsqrtf((float)(g_cnt[v] + 1));   // self-loop adds 1
    if (fq == 0) g_dinv[v] = dv;
    float4* hp = (float4*)&g_h[v * HID + fq * 4];
    float4 h = *hp;
    h.x *= dv; h.y *= dv; h.z *= dv; h.w *= dv;
    *hp = h;
}

// ---------------- GEMM1: h = x @ W1 ; 4 rows x 16 cols per thread ----------------
// 128 threads; thread t owns rows {t, t+128, t+256, t+384} of a 512-row tile.
// x broadcast-packed (a,a), W as genuine (col j, col j+1) pairs: 80B smem per
// thread-k for 64 MACs. LDS banks: xs stride 33 -> (t + k) % 32, conflict-free;
// wsd loads are warp-uniform broadcasts.
#define GROWS 512
#define GKT   32
#define XPAD  (GKT + 1)
__global__ __launch_bounds__(128) void k_gemm1(const float* __restrict__ x,
                                               const float* __restrict__ W1, int n) {
    __shared__ float xs[GROWS][XPAD];                          // 67.6 KB
    __shared__ __align__(16) unsigned long long wsd[GKT][8];   // col-pairs, 2 KB
    int t = threadIdx.x;
    int c = t & 7, rb = t >> 3;           // loader: k-chunk 0..7, row-base 0..15
    int r0 = blockIdx.x * GROWS;

    unsigned long long acc[4][8];
#pragma unroll
    for (int p = 0; p < 4; p++)
#pragma unroll
        for (int cp = 0; cp < 8; cp++) acc[p][cp] = 0ull;

    for (int kt = 0; kt < FIN; kt += GKT) {
        // W tile: genuine column pairs (col 2cp, col 2cp+1)
        for (int idx = t; idx < GKT * 8; idx += 128) {
            int kk = idx >> 3, cp = idx & 7;
            float w0 = W1[(kt + kk) * HID + cp * 2];
            float w1 = W1[(kt + kk) * HID + cp * 2 + 1];
            unsigned long long pw; PACK2(pw, w0, w1);
            wsd[kk][cp] = pw;
        }
        // x tile: rows rb+16i, k-chunk c: scalar stores, banks (row+4c+j)%32 CF
#pragma unroll
        for (int i = 0; i < GROWS / 16; i++) {
            int row = rb + 16 * i;
            int gr = r0 + row;
            float4 v = make_float4(0.f, 0.f, 0.f, 0.f);
            if (gr < n) v = *(const float4*)&x[(long)gr * FIN + kt + c * 4];
            xs[row][c * 4 + 0] = v.x;
            xs[row][c * 4 + 1] = v.y;
            xs[row][c * 4 + 2] = v.z;
            xs[row][c * 4 + 3] = v.w;
        }
        __syncthreads();
#pragma unroll
        for (int k = 0; k < GKT; k++) {
            float a0 = xs[t][k];
            float a1 = xs[t + 128][k];
            float a2 = xs[t + 256][k];
            float a3 = xs[t + 384][k];
            unsigned long long pa0, pa1, pa2, pa3;
            PACK2(pa0, a0, a0);
            PACK2(pa1, a1, a1);
            PACK2(pa2, a2, a2);
            PACK2(pa3, a3, a3);
#pragma unroll
            for (int cp = 0; cp < 8; cp++) {
                unsigned long long w = wsd[k][cp];
                FMA2(acc[0][cp], pa0, w, acc[0][cp]);
                FMA2(acc[1][cp], pa1, w, acc[1][cp]);
                FMA2(acc[2][cp], pa2, w, acc[2][cp]);
                FMA2(acc[3][cp], pa3, w, acc[3][cp]);
            }
        }
        __syncthreads();
    }

#pragma unroll
    for (int p = 0; p < 4; p++) {
        int gr = r0 + t + 128 * p;
        if (gr < n) {
            float o[16];
#pragma unroll
            for (int cp = 0; cp < 8; cp++)
                UNPACK2(o[cp * 2], o[cp * 2 + 1], acc[p][cp]);
#pragma unroll
            for (int q = 0; q < 4; q++)
                *(float4*)&g_h[gr * HID + q * 4] =
                    make_float4(o[q * 4], o[q * 4 + 1], o[q * 4 + 2], o[q * 4 + 3]);
        }
    }
}

// ---------------- gather 1: hs2 = dv * relu(dv*(Σ hs[nbr] + hs[self]) + b1) ----------------
// lane layout: slot = lane>>2 (8 slots), fq = lane&3 (4 float4 feature lanes); unroll x4
__global__ __launch_bounds__(256) void k_gather1(const float* __restrict__ b1, int n) {
    int v = blockIdx.x * 8 + (threadIdx.x >> 5);
    if (v >= n) return;
    int lane = threadIdx.x & 31;
    int slot = lane >> 2, fq = lane & 3;

    int beg = v << 7;
    int dg  = g_cnt[v];

    float4 acc = make_float4(0.f, 0.f, 0.f, 0.f);
    int j = slot;
    for (; j + 24 < dg; j += 32) {
        int s0 = __ldg(&g_col[beg + j]);
        int s1 = __ldg(&g_col[beg + j + 8]);
        int s2 = __ldg(&g_col[beg + j + 16]);
        int s3 = __ldg(&g_col[beg + j + 24]);
        float4 h0 = *(const float4*)&g_h[s0 * HID + fq * 4];
        float4 h1 = *(const float4*)&g_h[s1 * HID + fq * 4];
        float4 h2 = *(const float4*)&g_h[s2 * HID + fq * 4];
        float4 h3 = *(const float4*)&g_h[s3 * HID + fq * 4];
        acc.x += (h0.x + h1.x) + (h2.x + h3.x);
        acc.y += (h0.y + h1.y) + (h2.y + h3.y);
        acc.z += (h0.z + h1.z) + (h2.z + h3.z);
        acc.w += (h0.w + h1.w) + (h2.w + h3.w);
    }
#pragma unroll
    for (int u = 0; u < 3; u++) {
        int jj = j + u * 8;
        if (jj < dg) {
            int s = __ldg(&g_col[beg + jj]);
            float4 h = *(const float4*)&g_h[s * HID + fq * 4];
            acc.x += h.x; acc.y += h.y; acc.z += h.z; acc.w += h.w;
        }
    }
#pragma unroll
    for (int off = 4; off <= 16; off <<= 1) {
        acc.x += __shfl_xor_sync(0xffffffffu, acc.x, off);
        acc.y += __shfl_xor_sync(0xffffffffu, acc.y, off);
        acc.z += __shfl_xor_sync(0xffffffffu, acc.z, off);
        acc.w += __shfl_xor_sync(0xffffffffu, acc.w, off);
    }

    float dv = g_dinv[v];
    float4 self = *(const float4*)&g_h[v * HID + fq * 4];   // already dinv-scaled
    float4 bb   = *(const float4*)&b1[fq * 4];
    float4 o;
    o.x = dv * fmaxf(dv * (acc.x + self.x) + bb.x, 0.0f);
    o.y = dv * fmaxf(dv * (acc.y + self.y) + bb.y, 0.0f);
    o.z = dv * fmaxf(dv * (acc.z + self.z) + bb.z, 0.0f);
    o.w = dv * fmaxf(dv * (acc.w + self.w) + bb.w, 0.0f);
    if (lane < 4) *(float4*)&g_h2[v * HID + fq * 4] = o;
}

// ---------------- gather 2 + W2 + log_softmax; resets g_cnt to 0 ----------------
__global__ __launch_bounds__(256) void k_gather2_final(const float* __restrict__ W2,
                                                       const float* __restrict__ b2,
                                                       float* __restrict__ out, int n) {
    __shared__ float w2s[HID * NCLS];
    __shared__ float b2s[NCLS];
    int t = threadIdx.x;
    for (int idx = t; idx < HID * NCLS; idx += 256) w2s[idx] = W2[idx];
    if (t < NCLS) b2s[t] = b2[t];
    __syncthreads();

    int v = blockIdx.x * 8 + (t >> 5);
    if (v >= n) return;
    int lane = t & 31;
    int slot = lane >> 2, fq = lane & 3;

    int beg = v << 7;
    int dg  = g_cnt[v];
    if (lane == 0) g_cnt[v] = 0;   // restore invariant: cnt==0 at call exit

    float4 acc = make_float4(0.f, 0.f, 0.f, 0.f);
    int j = slot;
    for (; j + 24 < dg; j += 32) {
        int s0 = __ldg(&g_col[beg + j]);
        int s1 = __ldg(&g_col[beg + j + 8]);
        int s2 = __ldg(&g_col[beg + j + 16]);
        int s3 = __ldg(&g_col[beg + j + 24]);
        float4 h0 = *(const float4*)&g_h2[s0 * HID + fq * 4];
        float4 h1 = *(const float4*)&g_h2[s1 * HID + fq * 4];
        float4 h2 = *(const float4*)&g_h2[s2 * HID + fq * 4];
        float4 h3 = *(const float4*)&g_h2[s3 * HID + fq * 4];
        acc.x += (h0.x + h1.x) + (h2.x + h3.x);
        acc.y += (h0.y + h1.y) + (h2.y + h3.y);
        acc.z += (h0.z + h1.z) + (h2.z + h3.z);
        acc.w += (h0.w + h1.w) + (h2.w + h3.w);
    }
#pragma unroll
    for (int u = 0; u < 3; u++) {
        int jj = j + u * 8;
        if (jj < dg) {
            int s = __ldg(&g_col[beg + jj]);
            float4 h = *(const float4*)&g_h2[s * HID + fq * 4];
            acc.x += h.x; acc.y += h.y; acc.z += h.z; acc.w += h.w;
        }
    }
#pragma unroll
    for (int off = 4; off <= 16; off <<= 1) {
        acc.x += __shfl_xor_sync(0xffffffffu, acc.x, off);
        acc.y += __shfl_xor_sync(0xffffffffu, acc.y, off);
        acc.z += __shfl_xor_sync(0xffffffffu, acc.z, off);
        acc.w += __shfl_xor_sync(0xffffffffu, acc.w, off);
    }

    float dv = g_dinv[v];
    float4 self = *(const float4*)&g_h2[v * HID + fq * 4];
    float av[4];
    av[0] = dv * (acc.x + self.x);
    av[1] = dv * (acc.y + self.y);
    av[2] = dv * (acc.z + self.z);
    av[3] = dv * (acc.w + self.w);

    float a[HID];
#pragma unroll
    for (int k = 0; k < HID; k++)
        a[k] = __shfl_sync(0xffffffffu, av[k & 3], k >> 2);

    float v1 = b2s[lane];
#pragma unroll
    for (int k = 0; k < HID; k++) v1 += a[k] * w2s[k * NCLS + lane];

    float v2 = __int_as_float(0xff800000);  // -inf
    if (lane < 8) {
        int c2 = 32 + lane;
        v2 = b2s[c2];
#pragma unroll
        for (int k = 0; k < HID; k++) v2 += a[k] * w2s[k * NCLS + c2];
    }

    float m = fmaxf(v1, v2);
#pragma unroll
    for (int off = 16; off >= 1; off >>= 1)
        m = fmaxf(m, __shfl_xor_sync(0xffffffffu, m, off));

    float se = __expf(v1 - m) + ((lane < 8) ? __expf(v2 - m) : 0.0f);
#pragma unroll
    for (int off = 16; off >= 1; off >>= 1)
        se += __shfl_xor_sync(0xffffffffu, se, off);

    float lse = __logf(se);
    out[v * NCLS + lane] = v1 - m - lse;
    if (lane < 8) out[v * NCLS + 32 + lane] = v2 - m - lse;
}

extern "C" void kernel_launch(void* const* d_in, const int* in_sizes, int n_in,
                              void* d_out, int out_size) {
    const float* x  = (const float*)d_in[0];
    const float* W1 = (const float*)d_in[1];
    const float* b1 = (const float*)d_in[2];
    const float* W2 = (const float*)d_in[3];
    const float* b2 = (const float*)d_in[4];
    const int*   ei = (const int*)d_in[5];   // int32: JAX x64 disabled

    int n = in_sizes[0] / FIN;
    int e = in_sizes[5] / 2;
    if (n > NMAX) n = NMAX;
    if (e > EMAX) e = EMAX;

    int ep  = (e + 1) / 2;                 // edge pairs
    int eb  = (ep + 255) / 256;
    int gnb = (n + 7) / 8;                 // warp-per-node grids
    int snb = (n * 4 + 255) / 256;         // 4 lanes per row
    int ggb = (n + GROWS - 1) / GROWS;

    // One-time host-side stream/event setup (first call is outside capture).
    static cudaStream_t s2 = nullptr;
    static cudaEvent_t  evF = nullptr, evJ = nullptr;
    static int          tried = 0;
    if (!tried) {
        tried = 1;
        if (cudaStreamCreateWithFlags(&s2, cudaStreamNonBlocking) != cudaSuccess) s2 = nullptr;
        if (s2) {
            if (cudaEventCreateWithFlags(&evF, cudaEventDisableTiming) != cudaSuccess ||
                cudaEventCreateWithFlags(&evJ, cudaEventDisableTiming) != cudaSuccess) {
                s2 = nullptr;
            }
        }
    }

    if (s2) {
        // Fork: gemm1 on s2 overlaps bucket fill on stream 0.
        cudaEventRecord(evF, 0);
        cudaStreamWaitEvent(s2, evF, 0);
        k_gemm1<<<ggb, 128, 0, s2>>>(x, W1, n);
        cudaEventRecord(evJ, s2);

        k_fill<<<eb, 256>>>(ei, e);

        cudaStreamWaitEvent(0, evJ, 0);    // join: need h AND cnt
    } else {
        k_gemm1<<<ggb, 128>>>(x, W1, n);
        k_fill<<<eb, 256>>>(ei, e);
    }

    k_dinv_scale<<<snb, 256>>>(n);
    k_gather1<<<gnb, 256>>>(b1, n);
    k_gather2_final<<<gnb, 256>>>(W2, b2, (float*)d_out, n);
}